// round 3
// baseline (speedup 1.0000x reference)
#include <cuda_runtime.h>

// AdaptiveStdPooling2d: x [B=16, C=128, H=512, W=128] fp32
// kh = 64 (variance over height within bin), kw = 8 (sum of stds over width)
// out [B, C, 8, 16] fp32
//
// One warp per (b,c,ho) slab: 64 rows x 128 cols = 32KB contiguous.
// Lane l loads float4 -> columns 4l..4l+3 via __ldcs (evict-first stream).
// kw=8 = 2 lanes -> one shfl_xor.
//
// R3 change: single-wave launch. 16 CTAs/SM x 148 SMs = 2368 concurrent
// CTAs; grid=2048 (< 2368) with each warp handling 2 slabs removes the
// 73%-full second wave + wave-transition of the old grid=4096 launch.

#define EPS 1e-14f

__device__ __forceinline__ void process_slab(const float4* __restrict__ src,
                                             int lane,
                                             float* __restrict__ out,
                                             size_t out_base) {
    float s0 = 0.f, s1 = 0.f, s2 = 0.f, s3 = 0.f;
    float q0 = 0.f, q1 = 0.f, q2 = 0.f, q3 = 0.f;

#pragma unroll 16
    for (int r = 0; r < 64; ++r) {
        float4 v = __ldcs(src + (size_t)r * 32);  // streaming: evict-first
        s0 += v.x; q0 = fmaf(v.x, v.x, q0);
        s1 += v.y; q1 = fmaf(v.y, v.y, q1);
        s2 += v.z; q2 = fmaf(v.z, v.z, q2);
        s3 += v.w; q3 = fmaf(v.w, v.w, q3);
    }

    const float inv = 1.0f / 64.0f;
    float m0 = s0 * inv, m1 = s1 * inv, m2 = s2 * inv, m3 = s3 * inv;
    float v0 = fmaf(-m0, m0, q0 * inv);
    float v1 = fmaf(-m1, m1, q1 * inv);
    float v2 = fmaf(-m2, m2, q2 * inv);
    float v3 = fmaf(-m3, m3, q3 * inv);

    float ssum = sqrtf(v0 + EPS) + sqrtf(v1 + EPS) +
                 sqrtf(v2 + EPS) + sqrtf(v3 + EPS);

    // kw = 8 columns = 2 lanes (4 cols each): pairwise reduce
    ssum += __shfl_xor_sync(0xffffffffu, ssum, 1);

    if ((lane & 1) == 0) {
        out[out_base + (lane >> 1)] = ssum;
    }
}

__global__ __launch_bounds__(128)
void adaptive_std_pool_kernel(const float* __restrict__ x,
                              float* __restrict__ out) {
    const int warp0 = blockIdx.x * 4 + (threadIdx.x >> 5);  // first slab id
    const int lane = threadIdx.x & 31;
    const float4* __restrict__ base = reinterpret_cast<const float4*>(x);

    // Slab 1: warp0            Slab 2: warp0 + 8192
    process_slab(base + (size_t)warp0 * 2048 + lane, lane, out,
                 (size_t)warp0 * 16);
    const int wg2 = warp0 + 8192;
    process_slab(base + (size_t)wg2 * 2048 + lane, lane, out,
                 (size_t)wg2 * 16);
}

extern "C" void kernel_launch(void* const* d_in, const int* in_sizes, int n_in,
                              void* d_out, int out_size) {
    const float* x = (const float*)d_in[0];
    float* out = (float*)d_out;
    // 16384 slabs / 2 per warp = 8192 warps -> 2048 blocks x 128 threads
    adaptive_std_pool_kernel<<<2048, 128>>>(x, out);
}